// round 4
// baseline (speedup 1.0000x reference)
#include <cuda_runtime.h>

#define NQ 14
#define NSTATE (1 << NQ)
#define DEPTH 6
#define NTHREADS 512

typedef unsigned long long ull;

// ---------- packed f32x2 helpers ----------
__device__ __forceinline__ ull pack2(float lo, float hi) {
    ull r; asm("mov.b64 %0, {%1, %2};" : "=l"(r) : "f"(lo), "f"(hi)); return r;
}
__device__ __forceinline__ void unpack2(ull v, float& lo, float& hi) {
    asm("mov.b64 {%0, %1}, %2;" : "=f"(lo), "=f"(hi) : "l"(v));
}
__device__ __forceinline__ ull fma2(ull a, ull b, ull c) {
    ull d; asm("fma.rn.f32x2 %0, %1, %2, %3;" : "=l"(d) : "l"(a), "l"(b), "l"(c)); return d;
}
__device__ __forceinline__ float2 cmulf(float2 a, float2 b) {
    return make_float2(fmaf(a.x, b.x, -a.y * b.y), fmaf(a.x, b.y, a.y * b.x));
}

// gray decode (inverse of b ^ (b>>1)), 14-bit
__device__ __forceinline__ int gdec14(int v) {
    v ^= v >> 1; v ^= v >> 2; v ^= v >> 4; v ^= v >> 8; return v & (NSTATE - 1);
}

// RY via 3-shear lifting: [[c,s],[-s,c]] with t = s/(1+c).
// Uniform convention here: slot with gate-bit==k_G directly; pass (-s,-t).
template<int G>
__device__ __forceinline__ void apply_gate(ull (&r)[32], float s_signed, float t_signed) {
    const ull tt = pack2(t_signed, t_signed);
    const ull ns = pack2(-s_signed, -s_signed);
#pragma unroll
    for (int k = 0; k < 32; ++k) {
        if ((k & (1 << G)) == 0) {
            const int k2 = k | (1 << G);
            ull u = r[k], v = r[k2];
            u = fma2(tt, v, u);
            v = fma2(ns, u, v);
            u = fma2(tt, v, u);
            r[k] = u; r[k2] = v;
        }
    }
}

// P1 body after r[] holds elem(slab | lane<<5 | k): gates on bits 0..9 with an
// in-slab (warp-private) transpose; no block barrier anywhere inside.
// Global swizzle rule: elem j lives at st[j ^ ((j>>5)&31)].
__device__ __forceinline__ void phase1(ull (&r)[32], ull* st, const float2* gate,
                                       int l, int slab, int lane) {
    float2 g;
    g = gate[l*NQ+0]; apply_gate<0>(r, -g.x, -g.y);
    g = gate[l*NQ+1]; apply_gate<1>(r, -g.x, -g.y);
    g = gate[l*NQ+2]; apply_gate<2>(r, -g.x, -g.y);
    g = gate[l*NQ+3]; apply_gate<3>(r, -g.x, -g.y);
    g = gate[l*NQ+4]; apply_gate<4>(r, -g.x, -g.y);
    // transpose within own slab (exclusive ownership -> syncwarp suffices)
#pragma unroll
    for (int k = 0; k < 32; ++k) st[slab | (lane << 5) | (k ^ lane)] = r[k];
    __syncwarp();
#pragma unroll
    for (int k = 0; k < 32; ++k) r[k] = st[slab | (k << 5) | (lane ^ k)];
    g = gate[l*NQ+5]; apply_gate<0>(r, -g.x, -g.y);
    g = gate[l*NQ+6]; apply_gate<1>(r, -g.x, -g.y);
    g = gate[l*NQ+7]; apply_gate<2>(r, -g.x, -g.y);
    g = gate[l*NQ+8]; apply_gate<3>(r, -g.x, -g.y);
    g = gate[l*NQ+9]; apply_gate<4>(r, -g.x, -g.y);
    // store back canonical (same addresses each lane just read -> no race)
#pragma unroll
    for (int k = 0; k < 32; ++k) st[slab | (k << 5) | (lane ^ k)] = r[k];
}

__global__ void __launch_bounds__(NTHREADS, 1)
vqc_kernel(const float* __restrict__ x, const float* __restrict__ freq,
           const float* __restrict__ vp, float* __restrict__ out)
{
    extern __shared__ ull smem[];
    ull*    st   = smem;                         // 16384 amps, elem j at st[j ^ ((j>>5)&31)]
    float2* gate = (float2*)(st + NSTATE);       // [DEPTH][14] (sin(θ/2), tan(θ/4)) by bit pos
    float4* vv   = (float4*)(gate + DEPTH * NQ); // per-wire encoding 2-vector, by bit pos
    float*  red  = (float*)(vv + NQ);            // 16 warp partials

    const int tid  = threadIdx.x;
    const int lane = tid & 31;
    const int w    = tid >> 5;          // warp id = state bits 10..13 (own slab)
    const int slab = w << 10;
    const int bs   = blockIdx.x;

    // ---- setup ----
    if (tid < DEPTH * NQ) {
        int l = tid / NQ, wi = tid - l * NQ;
        int p = NQ - 1 - wi;                     // wire -> bit position (wire0 = MSB)
        float s, c;
        sincosf(0.5f * vp[tid], &s, &c);
        gate[l * NQ + p] = make_float2(s, s / (1.0f + c));
    }
    if (tid < NQ) {
        int wi = tid, p = NQ - 1 - wi;
        float xv = x[bs * NQ + wi];
        float s1, c1; sincosf(0.5f * xv, &s1, &c1);
        float s2, c2; sincosf(0.5f * freq[wi] * xv, &s2, &c2);
        const float inv = 0.7071067811865476f;
        float a0 = (c1 - s1) * inv, a1 = (c1 + s1) * inv;
        vv[p] = make_float4(c2 * a0, -s2 * a1, c2 * a1, -s2 * a0);
    }
    __syncthreads();

    const int wl = (w << 5) | lane;     // P2 low-10 bits of element index
    const int D  = gdec14(wl);          // per-thread scatter constant (bits 0..9)

    float acc = 0.0f;

    for (int l = 0; l < DEPTH; ++l) {
        ull r[32];
        if (l == 0) {
            // Build post-ladder-1 product state directly in slab layout:
            // amp(idx) = prod_p v_p[gray14(idx)_p], idx = slab | lane<<5 | k.
            const int ib = slab | (lane << 5);
            const int hb = ib ^ (ib >> 1);       // gray bits >=5 (bit4 handled via e)
            float2 phi = make_float2(1.0f, 0.0f);
#pragma unroll
            for (int p = 5; p < NQ; ++p) {
                float4 q = vv[p];
                float2 sel = ((hb >> p) & 1) ? make_float2(q.z, q.w) : make_float2(q.x, q.y);
                phi = cmulf(phi, sel);
            }
            const int e = (lane & 1) << 4;       // gray bit4 = k4 ^ lane0
            float2 wv0[5], wv1[5];
#pragma unroll
            for (int p = 0; p < 5; ++p) {
                float4 q = vv[p];
                bool eb = (e >> p) & 1;
                wv0[p] = eb ? make_float2(q.z, q.w) : make_float2(q.x, q.y);
                wv1[p] = eb ? make_float2(q.x, q.y) : make_float2(q.z, q.w);
            }
            float2 tmp[32];
            tmp[0] = cmulf(phi, wv0[0]);
            tmp[1] = cmulf(phi, wv1[0]);
#pragma unroll
            for (int p = 1; p < 5; ++p) {
                const int sz = 1 << p;
#pragma unroll
                for (int j = sz - 1; j >= 0; --j) {
                    float2 t = tmp[j];
                    tmp[j + sz] = cmulf(wv1[p], t);
                    tmp[j]      = cmulf(wv0[p], t);
                }
            }
#pragma unroll
            for (int k = 0; k < 32; ++k) {
                const int gk = k ^ (k >> 1);     // compile-time gray5(k)
                r[k] = pack2(tmp[gk].x, tmp[gk].y);
            }
        } else {
            // P1 load own slab: elem(slab | lane<<5 | k)
#pragma unroll
            for (int k = 0; k < 32; ++k)
                r[k] = st[slab | (lane << 5) | (k ^ lane)];
        }

        phase1(r, st, gate, l, slab, lane);      // gates 0..9, barrier-free
        __syncthreads();                         // barrier A: slabs visible block-wide

        // ---- P2: elem j = k<<9 | wl ; regs hold bits 9..13 ----
#pragma unroll
        for (int k = 0; k < 32; ++k) {
            const int j = (k << 9) | wl;
            r[k] = st[j ^ ((j >> 5) & 31)];
        }
        float2 g;
        g = gate[l*NQ+10]; apply_gate<1>(r, -g.x, -g.y);
        g = gate[l*NQ+11]; apply_gate<2>(r, -g.x, -g.y);
        g = gate[l*NQ+12]; apply_gate<3>(r, -g.x, -g.y);
        g = gate[l*NQ+13]; apply_gate<4>(r, -g.x, -g.y);

        if (l == DEPTH - 1) {
#pragma unroll
            for (int k = 0; k < 32; ++k) {
                float re, im; unpack2(r[k], re, im);
                float m = fmaf(re, re, im * im);
                acc += (k & 16) ? -m : m;        // bit13 (wire 0) = k bit 4
            }
        } else {
            __syncthreads();                     // barrier B: all P2 reads done
            // scatter = next layer's CNOT ladder: dest = gdec14(j), swizzled
#pragma unroll
            for (int k = 0; k < 32; ++k) {
                const int j2 = gdec14(k << 9) ^ D;   // gdec14(k<<9) folds to a constant
                st[j2 ^ ((j2 >> 5) & 31)] = r[k];
            }
            __syncthreads();                     // barrier C: scatter visible
        }
    }

    // ---- <Z_0> reduction ----
#pragma unroll
    for (int o = 16; o; o >>= 1) acc += __shfl_xor_sync(0xffffffffu, acc, o);
    if (lane == 0) red[w] = acc;
    __syncthreads();
    if (tid == 0) {
        float s = 0.0f;
#pragma unroll
        for (int wgi = 0; wgi < NTHREADS / 32; ++wgi) s += red[wgi];
        out[bs] = s;
    }
}

extern "C" void kernel_launch(void* const* d_in, const int* in_sizes, int n_in,
                              void* d_out, int out_size) {
    const float* x    = (const float*)d_in[0];
    const float* freq = (const float*)d_in[1];
    const float* vp   = (const float*)d_in[2];
    float* out = (float*)d_out;

    const int B = in_sizes[0] / NQ;  // 2048
    const size_t smem = (size_t)NSTATE * 8 + DEPTH * NQ * 8 + NQ * 16 + 64;

    cudaFuncSetAttribute(vqc_kernel, cudaFuncAttributeMaxDynamicSharedMemorySize, (int)smem);
    vqc_kernel<<<B, NTHREADS, smem>>>(x, freq, vp, out);
}

// round 5
// speedup vs baseline: 1.0005x; 1.0005x over previous
#include <cuda_runtime.h>

#define NQ 14
#define NSTATE (1 << NQ)
#define DEPTH 6
#define NTHREADS 512

typedef unsigned long long ull;

// ---------- packed f32x2 helpers ----------
__device__ __forceinline__ ull pack2(float lo, float hi) {
    ull r; asm("mov.b64 %0, {%1, %2};" : "=l"(r) : "f"(lo), "f"(hi)); return r;
}
__device__ __forceinline__ void unpack2(ull v, float& lo, float& hi) {
    asm("mov.b64 {%0, %1}, %2;" : "=f"(lo), "=f"(hi) : "l"(v));
}
__device__ __forceinline__ ull fma2(ull a, ull b, ull c) {
    ull d; asm("fma.rn.f32x2 %0, %1, %2, %3;" : "=l"(d) : "l"(a), "l"(b), "l"(c)); return d;
}
__device__ __forceinline__ float2 cmulf(float2 a, float2 b) {
    return make_float2(fmaf(a.x, b.x, -a.y * b.y), fmaf(a.x, b.y, a.y * b.x));
}

// gray decode (inverse of b ^ (b>>1)), 14-bit
__device__ __forceinline__ int gdec14(int v) {
    v ^= v >> 1; v ^= v >> 2; v ^= v >> 4; v ^= v >> 8; return v & (NSTATE - 1);
}

// RY via 3-shear lifting: [[c,s],[-s,c]] with t = s/(1+c).
// Uniform convention here: slot with gate-bit==k_G directly; pass (-s,-t).
template<int G>
__device__ __forceinline__ void apply_gate(ull (&r)[32], float s_signed, float t_signed) {
    const ull tt = pack2(t_signed, t_signed);
    const ull ns = pack2(-s_signed, -s_signed);
#pragma unroll
    for (int k = 0; k < 32; ++k) {
        if ((k & (1 << G)) == 0) {
            const int k2 = k | (1 << G);
            ull u = r[k], v = r[k2];
            u = fma2(tt, v, u);
            v = fma2(ns, u, v);
            u = fma2(tt, v, u);
            r[k] = u; r[k2] = v;
        }
    }
}

// P1 body after r[] holds elem(slab | lane<<5 | k): gates on bits 0..9 with an
// in-slab (warp-private) transpose; no block barrier anywhere inside.
// Global swizzle rule: elem j lives at st[j ^ ((j>>5)&31)].
__device__ __forceinline__ void phase1(ull (&r)[32], ull* st, const float2* gate,
                                       int l, int slab, int lane) {
    float2 g;
    g = gate[l*NQ+0]; apply_gate<0>(r, -g.x, -g.y);
    g = gate[l*NQ+1]; apply_gate<1>(r, -g.x, -g.y);
    g = gate[l*NQ+2]; apply_gate<2>(r, -g.x, -g.y);
    g = gate[l*NQ+3]; apply_gate<3>(r, -g.x, -g.y);
    g = gate[l*NQ+4]; apply_gate<4>(r, -g.x, -g.y);
    // transpose within own slab (exclusive ownership -> syncwarp suffices)
#pragma unroll
    for (int k = 0; k < 32; ++k) st[slab | (lane << 5) | (k ^ lane)] = r[k];
    __syncwarp();
#pragma unroll
    for (int k = 0; k < 32; ++k) r[k] = st[slab | (k << 5) | (lane ^ k)];
    g = gate[l*NQ+5]; apply_gate<0>(r, -g.x, -g.y);
    g = gate[l*NQ+6]; apply_gate<1>(r, -g.x, -g.y);
    g = gate[l*NQ+7]; apply_gate<2>(r, -g.x, -g.y);
    g = gate[l*NQ+8]; apply_gate<3>(r, -g.x, -g.y);
    g = gate[l*NQ+9]; apply_gate<4>(r, -g.x, -g.y);
    // store back canonical (same addresses each lane just read -> no race)
#pragma unroll
    for (int k = 0; k < 32; ++k) st[slab | (k << 5) | (lane ^ k)] = r[k];
}

__global__ void __launch_bounds__(NTHREADS, 1)
vqc_kernel(const float* __restrict__ x, const float* __restrict__ freq,
           const float* __restrict__ vp, float* __restrict__ out)
{
    extern __shared__ ull smem[];
    ull*    st   = smem;                         // 16384 amps, elem j at st[j ^ ((j>>5)&31)]
    float2* gate = (float2*)(st + NSTATE);       // [DEPTH][14] (sin(θ/2), tan(θ/4)) by bit pos
    float4* vv   = (float4*)(gate + DEPTH * NQ); // per-wire encoding 2-vector, by bit pos
    float*  red  = (float*)(vv + NQ);            // 16 warp partials

    const int tid  = threadIdx.x;
    const int lane = tid & 31;
    const int w    = tid >> 5;          // warp id = state bits 10..13 (own slab)
    const int slab = w << 10;
    const int bs   = blockIdx.x;

    // ---- setup ----
    if (tid < DEPTH * NQ) {
        int l = tid / NQ, wi = tid - l * NQ;
        int p = NQ - 1 - wi;                     // wire -> bit position (wire0 = MSB)
        float s, c;
        sincosf(0.5f * vp[tid], &s, &c);
        gate[l * NQ + p] = make_float2(s, s / (1.0f + c));
    }
    if (tid < NQ) {
        int wi = tid, p = NQ - 1 - wi;
        float xv = x[bs * NQ + wi];
        float s1, c1; sincosf(0.5f * xv, &s1, &c1);
        float s2, c2; sincosf(0.5f * freq[wi] * xv, &s2, &c2);
        const float inv = 0.7071067811865476f;
        float a0 = (c1 - s1) * inv, a1 = (c1 + s1) * inv;
        vv[p] = make_float4(c2 * a0, -s2 * a1, c2 * a1, -s2 * a0);
    }
    __syncthreads();

    const int wl = (w << 5) | lane;     // P2 low-10 bits of element index
    const int D  = gdec14(wl);          // per-thread scatter constant (bits 0..9)

    float acc = 0.0f;

    for (int l = 0; l < DEPTH; ++l) {
        ull r[32];
        if (l == 0) {
            // Build post-ladder-1 product state directly in slab layout:
            // amp(idx) = prod_p v_p[gray14(idx)_p], idx = slab | lane<<5 | k.
            const int ib = slab | (lane << 5);
            const int hb = ib ^ (ib >> 1);       // gray bits >=5 (bit4 handled via e)
            float2 phi = make_float2(1.0f, 0.0f);
#pragma unroll
            for (int p = 5; p < NQ; ++p) {
                float4 q = vv[p];
                float2 sel = ((hb >> p) & 1) ? make_float2(q.z, q.w) : make_float2(q.x, q.y);
                phi = cmulf(phi, sel);
            }
            const int e = (lane & 1) << 4;       // gray bit4 = k4 ^ lane0
            float2 wv0[5], wv1[5];
#pragma unroll
            for (int p = 0; p < 5; ++p) {
                float4 q = vv[p];
                bool eb = (e >> p) & 1;
                wv0[p] = eb ? make_float2(q.z, q.w) : make_float2(q.x, q.y);
                wv1[p] = eb ? make_float2(q.x, q.y) : make_float2(q.z, q.w);
            }
            float2 tmp[32];
            tmp[0] = cmulf(phi, wv0[0]);
            tmp[1] = cmulf(phi, wv1[0]);
#pragma unroll
            for (int p = 1; p < 5; ++p) {
                const int sz = 1 << p;
#pragma unroll
                for (int j = sz - 1; j >= 0; --j) {
                    float2 t = tmp[j];
                    tmp[j + sz] = cmulf(wv1[p], t);
                    tmp[j]      = cmulf(wv0[p], t);
                }
            }
#pragma unroll
            for (int k = 0; k < 32; ++k) {
                const int gk = k ^ (k >> 1);     // compile-time gray5(k)
                r[k] = pack2(tmp[gk].x, tmp[gk].y);
            }
        } else {
            // P1 load own slab: elem(slab | lane<<5 | k)
#pragma unroll
            for (int k = 0; k < 32; ++k)
                r[k] = st[slab | (lane << 5) | (k ^ lane)];
        }

        phase1(r, st, gate, l, slab, lane);      // gates 0..9, barrier-free
        __syncthreads();                         // barrier A: slabs visible block-wide

        // ---- P2: elem j = k<<9 | wl ; regs hold bits 9..13 ----
#pragma unroll
        for (int k = 0; k < 32; ++k) {
            const int j = (k << 9) | wl;
            r[k] = st[j ^ ((j >> 5) & 31)];
        }
        float2 g;
        g = gate[l*NQ+10]; apply_gate<1>(r, -g.x, -g.y);
        g = gate[l*NQ+11]; apply_gate<2>(r, -g.x, -g.y);
        g = gate[l*NQ+12]; apply_gate<3>(r, -g.x, -g.y);
        g = gate[l*NQ+13]; apply_gate<4>(r, -g.x, -g.y);

        if (l == DEPTH - 1) {
#pragma unroll
            for (int k = 0; k < 32; ++k) {
                float re, im; unpack2(r[k], re, im);
                float m = fmaf(re, re, im * im);
                acc += (k & 16) ? -m : m;        // bit13 (wire 0) = k bit 4
            }
        } else {
            __syncthreads();                     // barrier B: all P2 reads done
            // scatter = next layer's CNOT ladder: dest = gdec14(j), swizzled
#pragma unroll
            for (int k = 0; k < 32; ++k) {
                const int j2 = gdec14(k << 9) ^ D;   // gdec14(k<<9) folds to a constant
                st[j2 ^ ((j2 >> 5) & 31)] = r[k];
            }
            __syncthreads();                     // barrier C: scatter visible
        }
    }

    // ---- <Z_0> reduction ----
#pragma unroll
    for (int o = 16; o; o >>= 1) acc += __shfl_xor_sync(0xffffffffu, acc, o);
    if (lane == 0) red[w] = acc;
    __syncthreads();
    if (tid == 0) {
        float s = 0.0f;
#pragma unroll
        for (int wgi = 0; wgi < NTHREADS / 32; ++wgi) s += red[wgi];
        out[bs] = s;
    }
}

extern "C" void kernel_launch(void* const* d_in, const int* in_sizes, int n_in,
                              void* d_out, int out_size) {
    const float* x    = (const float*)d_in[0];
    const float* freq = (const float*)d_in[1];
    const float* vp   = (const float*)d_in[2];
    float* out = (float*)d_out;

    const int B = in_sizes[0] / NQ;  // 2048
    const size_t smem = (size_t)NSTATE * 8 + DEPTH * NQ * 8 + NQ * 16 + 64;

    cudaFuncSetAttribute(vqc_kernel, cudaFuncAttributeMaxDynamicSharedMemorySize, (int)smem);
    vqc_kernel<<<B, NTHREADS, smem>>>(x, freq, vp, out);
}